// round 1
// baseline (speedup 1.0000x reference)
#include <cuda_runtime.h>
#include <math.h>

#define Bn   4096
#define Lnn  4096
#define Hn   2048
#define Dn   128
#define D2n  256

// ---------------- scratch (static device globals; no runtime alloc) ----------------
__device__ float g_Xn[(size_t)Bn * Hn];     // LN output (reused q then r)
__device__ float g_Hb[(size_t)Bn * D2n];    // hidden after GELU (reused)
__device__ float g_Zq[(size_t)Bn * Dn];
__device__ float g_Zr[(size_t)Lnn * Dn];
__device__ float g_Rbar[(size_t)Bn * Dn];
__device__ float g_ent[Bn];

// ---------------- LayerNorm over H=2048, one row per block ----------------
__global__ void ln_kernel(const float* __restrict__ x, const float* __restrict__ g,
                          const float* __restrict__ b, float* __restrict__ out) {
    __shared__ float s[Hn];
    __shared__ float red[256];
    int row = blockIdx.x, tid = threadIdx.x;
    const float* xr = x + (size_t)row * Hn;
    float lsum = 0.f;
    for (int k = tid; k < Hn; k += 256) { float v = xr[k]; s[k] = v; lsum += v; }
    red[tid] = lsum; __syncthreads();
    for (int o = 128; o > 0; o >>= 1) { if (tid < o) red[tid] += red[tid + o]; __syncthreads(); }
    float mean = red[0] * (1.f / Hn);
    __syncthreads();
    float lsq = 0.f;
    for (int k = tid; k < Hn; k += 256) { float d = s[k] - mean; lsq += d * d; }
    red[tid] = lsq; __syncthreads();
    for (int o = 128; o > 0; o >>= 1) { if (tid < o) red[tid] += red[tid + o]; __syncthreads(); }
    float rstd = rsqrtf(red[0] * (1.f / Hn) + 1e-5f);
    float* orow = out + (size_t)row * Hn;
    for (int k = tid; k < Hn; k += 256) orow[k] = (s[k] - mean) * rstd * g[k] + b[k];
}

// ---------------- GEMM1 + GELU: C[M,256] = A[M,2048] @ W^T + bias, gelu ----------------
// BM=BN=64, BK=16, 16x16 threads, 4x4 microtile
__global__ void gemm1_gelu(const float* __restrict__ A, const float* __restrict__ W,
                           const float* __restrict__ bias, float* __restrict__ C) {
    __shared__ float As[16][64];
    __shared__ float Bs[16][64];
    int tid = threadIdx.x;
    int tx = tid & 15, ty = tid >> 4;
    int m0 = blockIdx.y * 64, n0 = blockIdx.x * 64;
    float acc[4][4] = {};
    int lr = tid >> 2, lk = (tid & 3) * 4;
    const float* Aptr = A + (size_t)(m0 + lr) * Hn + lk;
    const float* Wptr = W + (size_t)(n0 + lr) * Hn + lk;
    for (int k0 = 0; k0 < Hn; k0 += 16) {
        float4 a4 = *(const float4*)(Aptr + k0);
        float4 w4 = *(const float4*)(Wptr + k0);
        As[lk + 0][lr] = a4.x; As[lk + 1][lr] = a4.y; As[lk + 2][lr] = a4.z; As[lk + 3][lr] = a4.w;
        Bs[lk + 0][lr] = w4.x; Bs[lk + 1][lr] = w4.y; Bs[lk + 2][lr] = w4.z; Bs[lk + 3][lr] = w4.w;
        __syncthreads();
#pragma unroll
        for (int k = 0; k < 16; k++) {
            float4 av = *(const float4*)&As[k][ty * 4];
            float4 bv = *(const float4*)&Bs[k][tx * 4];
            float aa[4] = {av.x, av.y, av.z, av.w};
            float bb[4] = {bv.x, bv.y, bv.z, bv.w};
#pragma unroll
            for (int i = 0; i < 4; i++)
#pragma unroll
                for (int j = 0; j < 4; j++) acc[i][j] += aa[i] * bb[j];
        }
        __syncthreads();
    }
#pragma unroll
    for (int i = 0; i < 4; i++) {
        int m = m0 + ty * 4 + i;
#pragma unroll
        for (int j = 0; j < 4; j++) {
            int n = n0 + tx * 4 + j;
            float v = acc[i][j] + bias[n];
            v = 0.5f * v * (1.f + erff(v * 0.7071067811865475f));
            C[(size_t)m * D2n + n] = v;
        }
    }
}

// ---------------- GEMM2 + l2norm: Z[r,128] = l2n(H[r,256] @ W2^T + b2) ----------------
// 4 rows per block, 128 threads (one output column per thread)
__global__ void gemm2_l2n(const float* __restrict__ Hin, const float* __restrict__ W2,
                          const float* __restrict__ b2, float* __restrict__ Z) {
    __shared__ float hs[4][D2n];
    __shared__ float red[128];
    int r0 = blockIdx.x * 4, tid = threadIdx.x;
    for (int i = tid; i < 4 * D2n; i += 128) hs[i >> 8][i & 255] = Hin[(size_t)r0 * D2n + i];
    __syncthreads();
    float bj = b2[tid];
    float acc[4] = {bj, bj, bj, bj};
    const float* wrow = W2 + (size_t)tid * D2n;
    for (int k = 0; k < D2n; k += 4) {
        float4 w4 = *(const float4*)(wrow + k);
#pragma unroll
        for (int r = 0; r < 4; r++) {
            float4 h4 = *(const float4*)&hs[r][k];
            acc[r] += h4.x * w4.x + h4.y * w4.y + h4.z * w4.z + h4.w * w4.w;
        }
    }
    for (int r = 0; r < 4; r++) {
        __syncthreads();
        red[tid] = acc[r] * acc[r]; __syncthreads();
        for (int o = 64; o > 0; o >>= 1) { if (tid < o) red[tid] += red[tid + o]; __syncthreads(); }
        float nrm = fmaxf(sqrtf(red[0]), 1e-12f);
        Z[(size_t)(r0 + r) * Dn + tid] = acc[r] / nrm;
    }
}

// ---------------- Fused attention: softmax (no max needed, |s|<0.089), r_bar, entropy ----------------
#define BQ 16
#define BL 64
#define ZPAD 132
__global__ void attn_kernel(const float* __restrict__ Zq, const float* __restrict__ Zr,
                            float* __restrict__ Rbar, float* __restrict__ ent) {
    __shared__ float zqs[BQ][Dn];
    __shared__ float zrs[BL][ZPAD];
    __shared__ float ps[BQ][BL];
    int q0 = blockIdx.x * BQ;
    int tid = threadIdx.x;
    int q = tid >> 4;    // 0..15 query within block
    int j = tid & 15;    // 0..15 lane within q-group
    for (int i = tid; i < BQ * Dn; i += 256) zqs[i >> 7][i & 127] = Zq[(size_t)q0 * Dn + i];
    float Osum[8] = {};
    float zsum = 0.f, tsum = 0.f;
    const float scale = 0.08838834764831845f;  // 1/sqrt(128)
    for (int l0 = 0; l0 < Lnn; l0 += BL) {
        __syncthreads();
        for (int i = tid; i < BL * (Dn / 4); i += 256) {
            int lr = i >> 5;
            int c4 = (i & 31) * 4;
            float4 v = *(const float4*)&Zr[(size_t)(l0 + lr) * Dn + c4];
            zrs[lr][c4 + 0] = v.x; zrs[lr][c4 + 1] = v.y; zrs[lr][c4 + 2] = v.z; zrs[lr][c4 + 3] = v.w;
        }
        __syncthreads();
        // scores: thread computes l = j + 16*i, i = 0..3
        float sc[4] = {};
#pragma unroll 8
        for (int d = 0; d < Dn; d += 4) {
            float4 a4 = *(const float4*)&zqs[q][d];
#pragma unroll
            for (int i = 0; i < 4; i++) {
                float4 z = *(const float4*)&zrs[j + 16 * i][d];
                sc[i] += a4.x * z.x + a4.y * z.y + a4.z * z.z + a4.w * z.w;
            }
        }
#pragma unroll
        for (int i = 0; i < 4; i++) {
            float s = sc[i] * scale;
            float p = __expf(s);
            zsum += p; tsum += p * s;
            ps[q][j + 16 * i] = p;
        }
        __syncthreads();
        // PV: thread owns (q, d0 = j*8 .. +7)
        int d0 = j * 8;
#pragma unroll 8
        for (int l = 0; l < BL; l++) {
            float p = ps[q][l];
            float4 z0 = *(const float4*)&zrs[l][d0];
            float4 z1 = *(const float4*)&zrs[l][d0 + 4];
            Osum[0] += p * z0.x; Osum[1] += p * z0.y; Osum[2] += p * z0.z; Osum[3] += p * z0.w;
            Osum[4] += p * z1.x; Osum[5] += p * z1.y; Osum[6] += p * z1.z; Osum[7] += p * z1.w;
        }
    }
    // reduce zsum/tsum over the 16 lanes of this q-group
#pragma unroll
    for (int o = 1; o < 16; o <<= 1) {
        zsum += __shfl_xor_sync(0xffffffffu, zsum, o, 16);
        tsum += __shfl_xor_sync(0xffffffffu, tsum, o, 16);
    }
    if (j == 0) ent[q0 + q] = logf(zsum) - tsum / zsum;
    float sq = 0.f;
#pragma unroll
    for (int i = 0; i < 8; i++) sq += Osum[i] * Osum[i];
#pragma unroll
    for (int o = 1; o < 16; o <<= 1) sq += __shfl_xor_sync(0xffffffffu, sq, o, 16);
    float rn = 1.f / fmaxf(sqrtf(sq), 1e-12f);
    int d0 = j * 8;
#pragma unroll
    for (int i = 0; i < 8; i++) Rbar[(size_t)(q0 + q) * Dn + d0 + i] = Osum[i] * rn;
}

// ---------------- Final: dec MLP + scalar heads. 8 rows per block, 128 threads ----------------
__global__ void final_kernel(const float* __restrict__ Zq, const float* __restrict__ Rbar,
                             const float* __restrict__ ent,
                             const float* __restrict__ gd, const float* __restrict__ bd,
                             const float* __restrict__ W1d, const float* __restrict__ b1d,
                             const float* __restrict__ W2d, const float* __restrict__ b2d,
                             const float* __restrict__ beta, const float* __restrict__ Wlen,
                             const float* __restrict__ blen, float* __restrict__ out) {
    __shared__ float raw[8][D2n];
    __shared__ float nrm[8][D2n];
    __shared__ float part[8][128];
    __shared__ float coss[8];
    int r0 = blockIdx.x * 8, tid = threadIdx.x;
    for (int i = tid; i < 8 * Dn; i += 128) {
        int r = i >> 7, d = i & 127;
        raw[r][d] = Zq[(size_t)(r0 + r) * Dn + d];
        raw[r][128 + d] = Rbar[(size_t)(r0 + r) * Dn + d];
    }
    __syncthreads();
    int w = tid >> 5, lane = tid & 31;
#pragma unroll
    for (int rr = 0; rr < 2; rr++) {
        int r = 2 * w + rr;
        float cs = 0.f, sm = 0.f;
        for (int k = lane; k < D2n; k += 32) sm += raw[r][k];
        for (int k = lane; k < Dn; k += 32) cs += raw[r][k] * raw[r][128 + k];
#pragma unroll
        for (int o = 16; o > 0; o >>= 1) { sm += __shfl_xor_sync(~0u, sm, o); cs += __shfl_xor_sync(~0u, cs, o); }
        float mean = sm * (1.f / D2n);
        float vq = 0.f;
        for (int k = lane; k < D2n; k += 32) { float d = raw[r][k] - mean; vq += d * d; }
#pragma unroll
        for (int o = 16; o > 0; o >>= 1) vq += __shfl_xor_sync(~0u, vq, o);
        float rstd = rsqrtf(vq * (1.f / D2n) + 1e-5f);
        for (int k = lane; k < D2n; k += 32) nrm[r][k] = (raw[r][k] - mean) * rstd * gd[k] + bd[k];
        if (lane == 0) coss[r] = cs;
    }
    __syncthreads();
    float b1 = b1d[tid];
    float acc[8] = {b1, b1, b1, b1, b1, b1, b1, b1};
    const float* wrow = W1d + (size_t)tid * D2n;
    for (int k = 0; k < D2n; k += 4) {
        float4 w4 = *(const float4*)(wrow + k);
#pragma unroll
        for (int r = 0; r < 8; r++) {
            float4 h4 = *(const float4*)&nrm[r][k];
            acc[r] += h4.x * w4.x + h4.y * w4.y + h4.z * w4.z + h4.w * w4.w;
        }
    }
    float w2 = W2d[tid];
#pragma unroll
    for (int r = 0; r < 8; r++) {
        float v = acc[r];
        v = 0.5f * v * (1.f + erff(v * 0.7071067811865475f));
        part[r][tid] = v * w2;
    }
    __syncthreads();
#pragma unroll
    for (int rr = 0; rr < 2; rr++) {
        int r = 2 * w + rr;
        float s = 0.f;
        for (int k = lane; k < 128; k += 32) s += part[r][k];
#pragma unroll
        for (int o = 16; o > 0; o >>= 1) s += __shfl_xor_sync(~0u, s, o);
        if (lane == 0) {
            float raw_logit = s + b2d[0];
            float u = ent[r0 + r] * (1.f / logf((float)Lnn));
            float cs = coss[r];
            float dl = Wlen[0] * cs + Wlen[1] * u + blen[0];
            float lf = tanhf(dl);
            float dt = beta[0] * u + beta[1] * lf;
            dt = fminf(fmaxf(dt, -0.5f), 0.5f);
            out[r0 + r] = raw_logit;
            out[Bn + r0 + r] = dt;
        }
    }
}

// ---------------- host launcher ----------------
extern "C" void kernel_launch(void* const* d_in, const int* in_sizes, int n_in,
                              void* d_out, int out_size) {
    const float* q     = (const float*)d_in[0];
    const float* R     = (const float*)d_in[1];
    const float* lnqg  = (const float*)d_in[2];
    const float* lnqb  = (const float*)d_in[3];
    const float* W1q   = (const float*)d_in[4];
    const float* b1q   = (const float*)d_in[5];
    const float* W2q   = (const float*)d_in[6];
    const float* b2q   = (const float*)d_in[7];
    const float* lnrg  = (const float*)d_in[8];
    const float* lnrb  = (const float*)d_in[9];
    const float* W1r   = (const float*)d_in[10];
    const float* b1r   = (const float*)d_in[11];
    const float* W2r   = (const float*)d_in[12];
    const float* b2r   = (const float*)d_in[13];
    const float* lndg  = (const float*)d_in[14];
    const float* lndb  = (const float*)d_in[15];
    const float* W1d   = (const float*)d_in[16];
    const float* b1d   = (const float*)d_in[17];
    const float* W2d   = (const float*)d_in[18];
    const float* b2d   = (const float*)d_in[19];
    const float* beta  = (const float*)d_in[20];
    const float* Wlen  = (const float*)d_in[21];
    const float* blen  = (const float*)d_in[22];
    float* out = (float*)d_out;

    float *xn, *hb, *zq, *zr, *rb, *en;
    cudaGetSymbolAddress((void**)&xn, g_Xn);
    cudaGetSymbolAddress((void**)&hb, g_Hb);
    cudaGetSymbolAddress((void**)&zq, g_Zq);
    cudaGetSymbolAddress((void**)&zr, g_Zr);
    cudaGetSymbolAddress((void**)&rb, g_Rbar);
    cudaGetSymbolAddress((void**)&en, g_ent);

    dim3 g1(D2n / 64, Bn / 64);

    // q path
    ln_kernel<<<Bn, 256>>>(q, lnqg, lnqb, xn);
    gemm1_gelu<<<g1, 256>>>(xn, W1q, b1q, hb);
    gemm2_l2n<<<Bn / 4, 128>>>(hb, W2q, b2q, zq);
    // r path (reuses xn/hb scratch; same-stream ordering makes this safe)
    ln_kernel<<<Lnn, 256>>>(R, lnrg, lnrb, xn);
    gemm1_gelu<<<g1, 256>>>(xn, W1r, b1r, hb);
    gemm2_l2n<<<Lnn / 4, 128>>>(hb, W2r, b2r, zr);
    // attention + entropy + r_bar
    attn_kernel<<<Bn / BQ, 256>>>(zq, zr, rb, en);
    // decision MLP + scalar heads
    final_kernel<<<Bn / 8, 128>>>(zq, rb, en, lndg, lndb, W1d, b1d, W2d, b2d,
                                  beta, Wlen, blen, out);
}